// round 15
// baseline (speedup 1.0000x reference)
#include <cuda_runtime.h>
#include <cuda_fp16.h>
#include <cstdint>
#include <math.h>

#define D_MODEL 1024
#define B_SZ 4
#define T_SZ 4096
#define NROWS (B_SZ * T_SZ)          /* 16384 */
#define CHUNK 512
#define NCHUNK (T_SZ / CHUNK)        /* 8 */
#define NUNITS (B_SZ * NCHUNK)       /* 32 */
#define LN_EPS 1e-5f
#define DEN_EPS 1e-6f
#define PGRID 304                    /* 2 CTAs x 152 SMs */

// ---------------- scratch (device globals; no allocations allowed) -----------
__device__ __half g_xnh[(size_t)NROWS * D_MODEL];
__device__ __half g_qkvh[(size_t)NROWS * 4 * D_MODEL];
__device__ __half g_kT[(size_t)B_SZ * D_MODEL * T_SZ];
__device__ __half g_vT[(size_t)B_SZ * D_MODEL * T_SZ];
__device__ __half g_Ph[(size_t)NUNITS * D_MODEL * D_MODEL];
__device__ float  g_Pk[NUNITS * D_MODEL];
__device__ __half g_attnh[(size_t)NUNITS * CHUNK * CHUNK];
__device__ __half g_numh[(size_t)NROWS * D_MODEL];
__device__ float  g_den[NROWS];
__device__ __half g_wth[(size_t)4096 * 1024];
__device__ __half g_wph[(size_t)1024 * 1024];
__device__ float  g_bcat[4096];

// tril block map for 512x512 attn tile (10 blocks of 128x128)
__constant__ int c_bm[10] = {0, 1, 1, 2, 2, 2, 3, 3, 3, 3};
__constant__ int c_bn[10] = {0, 0, 1, 0, 1, 2, 0, 1, 2, 3};

// ---------------- helpers -----------------------------------------------------
__device__ __forceinline__ uint32_t smem_u32(const void* p) {
    uint32_t a;
    asm("{ .reg .u64 t; cvta.to.shared.u64 t, %1; cvt.u32.u64 %0, t; }" : "=r"(a) : "l"(p));
    return a;
}

#define CP16(dst, src) \
    asm volatile("cp.async.cg.shared.global [%0], [%1], 16;" :: "r"(dst), "l"(src))
#define CP_COMMIT() asm volatile("cp.async.commit_group;" ::: "memory")
#define CP_WAIT(n)  asm volatile("cp.async.wait_group %0;" :: "n"(n) : "memory")

#define LDM4(r0, r1, r2, r3, addr) \
    asm volatile("ldmatrix.sync.aligned.m8n8.x4.shared.b16 {%0,%1,%2,%3}, [%4];" \
                 : "=r"(r0), "=r"(r1), "=r"(r2), "=r"(r3) : "r"(addr))

#define MMA16(c, a, b) \
    asm volatile( \
        "mma.sync.aligned.m16n8k16.row.col.f32.f16.f16.f32 " \
        "{%0,%1,%2,%3}, {%4,%5,%6,%7}, {%8,%9}, {%0,%1,%2,%3};" \
        : "+f"((c)[0]), "+f"((c)[1]), "+f"((c)[2]), "+f"((c)[3]) \
        : "r"((a)[0]), "r"((a)[1]), "r"((a)[2]), "r"((a)[3]), \
          "r"((b)[0]), "r"((b)[1]))

#define STB 32768                   /* stage bytes: A 16KB + B 16KB */
#define SMEM_BYTES (3 * STB)        /* 98304 */

// Common warp/fragment indexing for the 128x128 tile, 8 warps (2M x 4N)
struct TileIdx {
    int lane, w, wm, wn, g, lr, l4q, lmq, cxA, cxB;
    int rA[4], rB[2];
    __device__ __forceinline__ TileIdx(int tid) {
        lane = tid & 31; w = tid >> 5;
        wm = (w & 1) * 64; wn = (w >> 1) * 32;
        g = lane >> 3; lr = lane & 7;
        l4q = lane >> 2; lmq = lane & 3;
        cxA = (g >> 1); cxB = (g & 1);
#pragma unroll
        for (int mt = 0; mt < 4; mt++) rA[mt] = (wm + mt * 16 + lr + 8 * (g & 1)) * 128;
#pragma unroll
        for (int p = 0; p < 2; p++) rB[p] = (wn + p * 16 + lr + 8 * (g >> 1)) * 128;
    }
};

// ---------------- persistent unbatched GEMM (EPI 1: bias+f32, 5: bias+half) ---
// One continuous cp.async pipeline across tiles: lookahead 2 flat (tile,ktile)
// steps, one commit per iteration (empty at tail) so CP_WAIT(1) is uniform.
template <int EPI>
__global__ void __launch_bounds__(256, 2) pgemm(
    const __half* __restrict__ A, int lda,
    const __half* __restrict__ B, int ldb,
    void* __restrict__ C, int ldc,
    const float* __restrict__ bias, int K,
    int nxshift, int nxmask, int ntiles) {
    extern __shared__ char sm[];
    const uint32_t su = smem_u32(sm);
    const int tid = threadIdx.x;
    const TileIdx ti(tid);
    const int KT = K >> 6;
    const int G = gridDim.x;

    int tl = blockIdx.x, ktl = 0;   // load-side cursor

    auto issue_loads = [&](int stg) {
        if (tl < ntiles) {
            int m0 = (tl >> nxshift) * 128;
            int n0 = (tl & nxmask) * 128;
            uint32_t dstA = su + stg * STB;
            uint32_t dstB = dstA + 16384;
            int k0 = ktl * 64;
#pragma unroll
            for (int p = 0; p < 4; p++) {
                int c = tid + p * 256;
                int row = c >> 3, ch = c & 7;
                uint32_t off = row * 128 + ((ch ^ (row & 7)) << 4);
                CP16(dstA + off, A + (long long)(m0 + row) * lda + k0 + ch * 8);
                CP16(dstB + off, B + (long long)(n0 + row) * ldb + k0 + ch * 8);
            }
        }
        CP_COMMIT();
        if (++ktl == KT) { ktl = 0; tl += G; }
    };

    issue_loads(0);
    issue_loads(1);

    float acc[4][4][4];
#pragma unroll
    for (int mt = 0; mt < 4; mt++)
#pragma unroll
        for (int nt = 0; nt < 4; nt++)
#pragma unroll
            for (int r = 0; r < 4; r++) acc[mt][nt][r] = 0.f;

    int st = 0;
    for (int tc = blockIdx.x; tc < ntiles; tc += G) {
        for (int kt = 0; kt < KT; kt++) {
            CP_WAIT(1);
            __syncthreads();
            int stn = st + 2; if (stn >= 3) stn -= 3;
            issue_loads(stn);
            uint32_t Abase = su + st * STB;
            uint32_t Bbase = Abase + 16384;
            st = (st == 2) ? 0 : st + 1;
#pragma unroll
            for (int kk = 0; kk < 4; kk++) {
                uint32_t af[4][4], bf[4][2];
                int cA = ((kk * 2 + ti.cxA) ^ ti.lr) << 4;
                int cB = ((kk * 2 + ti.cxB) ^ ti.lr) << 4;
#pragma unroll
                for (int mt = 0; mt < 4; mt++)
                    LDM4(af[mt][0], af[mt][1], af[mt][2], af[mt][3], Abase + ti.rA[mt] + cA);
                LDM4(bf[0][0], bf[0][1], bf[1][0], bf[1][1], Bbase + ti.rB[0] + cB);
                LDM4(bf[2][0], bf[2][1], bf[3][0], bf[3][1], Bbase + ti.rB[1] + cB);
#pragma unroll
                for (int mt = 0; mt < 4; mt++)
#pragma unroll
                    for (int nt = 0; nt < 4; nt++)
                        MMA16(acc[mt][nt], af[mt], bf[nt]);
            }
        }
        // ---- epilogue for tile tc (next tile's loads stream underneath) ----
        {
            int m0 = (tc >> nxshift) * 128;
            int n0 = (tc & nxmask) * 128;
            float* Cf = (float*)C;
            __half* Ch = (__half*)C;
#pragma unroll
            for (int mt = 0; mt < 4; mt++) {
                int row0 = m0 + ti.wm + mt * 16 + ti.l4q;
                int row1 = row0 + 8;
#pragma unroll
                for (int nt = 0; nt < 4; nt++) {
                    int col = n0 + ti.wn + nt * 8 + ti.lmq * 2;
                    float b0 = bias[col], b1 = bias[col + 1];
                    float v0 = acc[mt][nt][0] + b0, v1 = acc[mt][nt][1] + b1;
                    float v2 = acc[mt][nt][2] + b0, v3 = acc[mt][nt][3] + b1;
                    if (EPI == 1) {
                        *reinterpret_cast<float2*>(Cf + (long long)row0 * ldc + col) = make_float2(v0, v1);
                        *reinterpret_cast<float2*>(Cf + (long long)row1 * ldc + col) = make_float2(v2, v3);
                    } else {
                        *reinterpret_cast<__half2*>(Ch + (long long)row0 * ldc + col) = __floats2half2_rn(v0, v1);
                        *reinterpret_cast<__half2*>(Ch + (long long)row1 * ldc + col) = __floats2half2_rn(v2, v3);
                    }
                    acc[mt][nt][0] = 0.f; acc[mt][nt][1] = 0.f;
                    acc[mt][nt][2] = 0.f; acc[mt][nt][3] = 0.f;
                }
            }
        }
    }
}

// ---------------- batched fp16 GEMM (EPI 2: P half out, 3: attn masked) -------
template <int EPI>
__global__ void __launch_bounds__(256, 2) hgemm(
    const __half* __restrict__ A, int lda, long long sAb, long long sAc,
    const __half* __restrict__ B, int ldb, long long sBb, long long sBc,
    void* __restrict__ C, int ldc, long long sC,
    const float* __restrict__ bias, float* __restrict__ den, int K) {
    extern __shared__ char sm[];
    const uint32_t su = smem_u32(sm);
    const int tid = threadIdx.x;
    const int u = blockIdx.z;
    const int ub = u >> 3, uc = u & 7;

    if (EPI == 2 && uc == NCHUNK - 1) return;   // last chunk's P never consumed

    const __half* Ab = A + ub * sAb + uc * sAc;
    const __half* Bb = B + ub * sBb + uc * sBc;
    int m0, n0;
    if (EPI == 3) { m0 = c_bm[blockIdx.x] * 128; n0 = c_bn[blockIdx.x] * 128; }
    else          { m0 = blockIdx.y * 128;       n0 = blockIdx.x * 128; }

    const TileIdx ti(tid);

    auto loadA = [&](int st, int kt) {
        uint32_t dst = su + st * STB;
        int k0 = kt * 64;
#pragma unroll
        for (int p = 0; p < 4; p++) {
            int c = tid + p * 256;
            int row = c >> 3, ch = c & 7;
            const __half* src = Ab + (long long)(m0 + row) * lda + k0 + ch * 8;
            CP16(dst + row * 128 + ((ch ^ (row & 7)) << 4), src);
        }
    };
    auto loadB = [&](int st, int kt) {
        uint32_t dst = su + st * STB + 16384;
        int k0 = kt * 64;
#pragma unroll
        for (int p = 0; p < 4; p++) {
            int c = tid + p * 256;
            int row = c >> 3, ch = c & 7;
            const __half* src = Bb + (long long)(n0 + row) * ldb + k0 + ch * 8;
            CP16(dst + row * 128 + ((ch ^ (row & 7)) << 4), src);
        }
    };

    float acc[4][4][4];
#pragma unroll
    for (int mt = 0; mt < 4; mt++)
#pragma unroll
        for (int nt = 0; nt < 4; nt++)
#pragma unroll
            for (int r = 0; r < 4; r++) acc[mt][nt][r] = 0.f;

    const int KT = K >> 6;
    loadA(0, 0); loadB(0, 0); CP_COMMIT();
    if (KT > 1) { loadA(1, 1); loadB(1, 1); CP_COMMIT(); }

    int st = 0, stn = 2;
    for (int i = 0; i < KT; i++) {
        if (i < KT - 1) { CP_WAIT(1); } else { CP_WAIT(0); }
        __syncthreads();
        if (i + 2 < KT) {
            loadA(stn, i + 2); loadB(stn, i + 2); CP_COMMIT();
            stn = (stn == 2) ? 0 : stn + 1;
        }
        uint32_t Abase = su + st * STB;
        uint32_t Bbase = Abase + 16384;
        st = (st == 2) ? 0 : st + 1;
#pragma unroll
        for (int kk = 0; kk < 4; kk++) {
            uint32_t af[4][4], bf[4][2];
            int cA = ((kk * 2 + ti.cxA) ^ ti.lr) << 4;
            int cB = ((kk * 2 + ti.cxB) ^ ti.lr) << 4;
#pragma unroll
            for (int mt = 0; mt < 4; mt++)
                LDM4(af[mt][0], af[mt][1], af[mt][2], af[mt][3], Abase + ti.rA[mt] + cA);
            LDM4(bf[0][0], bf[0][1], bf[1][0], bf[1][1], Bbase + ti.rB[0] + cB);
            LDM4(bf[2][0], bf[2][1], bf[3][0], bf[3][1], Bbase + ti.rB[1] + cB);
#pragma unroll
            for (int mt = 0; mt < 4; mt++)
#pragma unroll
                for (int nt = 0; nt < 4; nt++)
                    MMA16(acc[mt][nt], af[mt], bf[nt]);
        }
    }

    // ---- epilogue ----
    __half* Ch = (__half*)C + (long long)u * sC;

#pragma unroll
    for (int mt = 0; mt < 4; mt++) {
        int row0 = m0 + ti.wm + mt * 16 + ti.l4q;
        int row1 = row0 + 8;
        float rs0 = 0.f, rs1 = 0.f;
#pragma unroll
        for (int nt = 0; nt < 4; nt++) {
            int col = n0 + ti.wn + nt * 8 + ti.lmq * 2;
            float v0 = acc[mt][nt][0], v1 = acc[mt][nt][1];
            float v2 = acc[mt][nt][2], v3 = acc[mt][nt][3];
            if (EPI == 3) {
                v0 = (col     > row0) ? 0.f : v0;
                v1 = (col + 1 > row0) ? 0.f : v1;
                v2 = (col     > row1) ? 0.f : v2;
                v3 = (col + 1 > row1) ? 0.f : v3;
            }
            __half2 h0 = __floats2half2_rn(v0, v1);
            __half2 h1 = __floats2half2_rn(v2, v3);
            if (EPI == 3) {
                rs0 += __half2float(h0.x) + __half2float(h0.y);
                rs1 += __half2float(h1.x) + __half2float(h1.y);
            }
            *reinterpret_cast<__half2*>(Ch + (long long)row0 * ldc + col) = h0;
            *reinterpret_cast<__half2*>(Ch + (long long)row1 * ldc + col) = h1;
        }
        if (EPI == 3) {
            rs0 += __shfl_xor_sync(0xffffffffu, rs0, 1);
            rs0 += __shfl_xor_sync(0xffffffffu, rs0, 2);
            rs1 += __shfl_xor_sync(0xffffffffu, rs1, 1);
            rs1 += __shfl_xor_sync(0xffffffffu, rs1, 2);
            if (ti.lmq == 0) {
                atomicAdd(den + (long long)u * CHUNK + row0, rs0);
                atomicAdd(den + (long long)u * CHUNK + row1, rs1);
            }
        }
    }
}

// ---------------- fused num kernel: num = (Q@S + attn@V) / den -> fp16 --------
__global__ void __launch_bounds__(256, 2) num_kernel(
    const __half* __restrict__ qkvh, const __half* __restrict__ Ph,
    const __half* __restrict__ attnh, const __half* __restrict__ vT,
    const float* __restrict__ den, __half* __restrict__ numh) {
    extern __shared__ char sm[];
    const uint32_t su = smem_u32(sm);
    const int tid = threadIdx.x;
    const int u = blockIdx.z;
    const int ub = u >> 3, uc = u & 7;
    const int m0 = blockIdx.y * 128;
    const int n0 = blockIdx.x * 128;
    const TileIdx ti(tid);

    float acc[4][4][4];
#pragma unroll
    for (int mt = 0; mt < 4; mt++)
#pragma unroll
        for (int nt = 0; nt < 4; nt++)
#pragma unroll
            for (int r = 0; r < 4; r++) acc[mt][nt][r] = 0.f;

    auto phase = [&](const __half* Ab, int lda, const __half* Bb, int ldb, int KT) {
        __syncthreads();   // stage-reuse guard at phase boundary
        auto loadA = [&](int st, int kt) {
            uint32_t dst = su + st * STB;
            int k0 = kt * 64;
#pragma unroll
            for (int p = 0; p < 4; p++) {
                int c = tid + p * 256;
                int row = c >> 3, ch = c & 7;
                const __half* src = Ab + (long long)(m0 + row) * lda + k0 + ch * 8;
                CP16(dst + row * 128 + ((ch ^ (row & 7)) << 4), src);
            }
        };
        auto loadB = [&](int st, int kt) {
            uint32_t dst = su + st * STB + 16384;
            int k0 = kt * 64;
#pragma unroll
            for (int p = 0; p < 4; p++) {
                int c = tid + p * 256;
                int row = c >> 3, ch = c & 7;
                const __half* src = Bb + (long long)(n0 + row) * ldb + k0 + ch * 8;
                CP16(dst + row * 128 + ((ch ^ (row & 7)) << 4), src);
            }
        };
        loadA(0, 0); loadB(0, 0); CP_COMMIT();
        if (KT > 1) { loadA(1, 1); loadB(1, 1); CP_COMMIT(); }
        int st = 0, stn = 2;
        for (int i = 0; i < KT; i++) {
            if (i < KT - 1) { CP_WAIT(1); } else { CP_WAIT(0); }
            __syncthreads();
            if (i + 2 < KT) {
                loadA(stn, i + 2); loadB(stn, i + 2); CP_COMMIT();
                stn = (stn == 2) ? 0 : stn + 1;
            }
            uint32_t Abase = su + st * STB;
            uint32_t Bbase = Abase + 16384;
            st = (st == 2) ? 0 : st + 1;
#pragma unroll
            for (int kk = 0; kk < 4; kk++) {
                uint32_t af[4][4], bf[4][2];
                int cA = ((kk * 2 + ti.cxA) ^ ti.lr) << 4;
                int cB = ((kk * 2 + ti.cxB) ^ ti.lr) << 4;
#pragma unroll
                for (int mt = 0; mt < 4; mt++)
                    LDM4(af[mt][0], af[mt][1], af[mt][2], af[mt][3], Abase + ti.rA[mt] + cA);
                LDM4(bf[0][0], bf[0][1], bf[1][0], bf[1][1], Bbase + ti.rB[0] + cB);
                LDM4(bf[2][0], bf[2][1], bf[3][0], bf[3][1], Bbase + ti.rB[1] + cB);
#pragma unroll
                for (int mt = 0; mt < 4; mt++)
#pragma unroll
                    for (int nt = 0; nt < 4; nt++)
                        MMA16(acc[mt][nt], af[mt], bf[nt]);
            }
        }
    };

    // Phase 1: Q @ S   (S_0 = 0 -> skip for first chunk of each batch)
    if (uc != 0)
        phase(qkvh + (long long)u * CHUNK * 4096, 4096,
              Ph + (long long)u * 1048576, 1024, 16);
    // Phase 2: attn @ V  (causal-truncated K)
    int K2 = m0 + 128;
    phase(attnh + (long long)u * CHUNK * CHUNK, CHUNK,
          vT + (long long)ub * 4194304 + uc * CHUNK, 4096, K2 >> 6);

    // epilogue: / den -> fp16
    __half* Ch = numh + (long long)u * CHUNK * 1024;
#pragma unroll
    for (int mt = 0; mt < 4; mt++) {
        int row0 = m0 + ti.wm + mt * 16 + ti.l4q;
        int row1 = row0 + 8;
        float rcp0 = __frcp_rn(den[(long long)u * CHUNK + row0]);
        float rcp1 = __frcp_rn(den[(long long)u * CHUNK + row1]);
#pragma unroll
        for (int nt = 0; nt < 4; nt++) {
            int col = n0 + ti.wn + nt * 8 + ti.lmq * 2;
            __half2 h0 = __floats2half2_rn(acc[mt][nt][0] * rcp0, acc[mt][nt][1] * rcp0);
            __half2 h1 = __floats2half2_rn(acc[mt][nt][2] * rcp1, acc[mt][nt][3] * rcp1);
            *reinterpret_cast<__half2*>(Ch + (long long)row0 * 1024 + col) = h0;
            *reinterpret_cast<__half2*>(Ch + (long long)row1 * 1024 + col) = h1;
        }
    }
}

// ---------------- LayerNorm -> fp16 -------------------------------------------
__global__ void ln_kernel(const float* __restrict__ x,
                          const float* __restrict__ g,
                          const float* __restrict__ b,
                          __half* __restrict__ xn) {
    int row = blockIdx.x;
    const float* xr = x + (size_t)row * D_MODEL;
    __half* outr = xn + (size_t)row * D_MODEL;
    int tid = threadIdx.x;
    float vals[4];
    float s = 0.f, ss = 0.f;
#pragma unroll
    for (int i = 0; i < 4; i++) {
        float v = xr[tid + i * 256];
        vals[i] = v; s += v; ss += v * v;
    }
#pragma unroll
    for (int o = 16; o > 0; o >>= 1) {
        s  += __shfl_xor_sync(0xffffffffu, s, o);
        ss += __shfl_xor_sync(0xffffffffu, ss, o);
    }
    __shared__ float sbuf[8], ssbuf[8];
    int warp = tid >> 5, lane = tid & 31;
    if (lane == 0) { sbuf[warp] = s; ssbuf[warp] = ss; }
    __syncthreads();
    float ts = 0.f, tss = 0.f;
#pragma unroll
    for (int wq = 0; wq < 8; wq++) { ts += sbuf[wq]; tss += ssbuf[wq]; }
    float mu = ts * (1.0f / D_MODEL);
    float var = tss * (1.0f / D_MODEL) - mu * mu;
    float inv = rsqrtf(var + LN_EPS);
#pragma unroll
    for (int i = 0; i < 4; i++) {
        int d = tid + i * 256;
        outr[d] = __float2half_rn((vals[i] - mu) * inv * g[d] + b[d]);
    }
}

// ---------------- weight prepack (fp16, transposed) ---------------------------
__global__ void pack_w(const float* __restrict__ wq, const float* __restrict__ wg,
                       __half* __restrict__ wt) {
    long long idx = (long long)blockIdx.x * 256 + threadIdx.x;  // n*1024 + k
    int n = (int)(idx >> 10);
    int k = (int)(idx & 1023);
    float v = (n < 3072) ? wq[(long long)k * 3072 + n] : wg[(long long)k * 1024 + n - 3072];
    wt[idx] = __float2half_rn(v);
}
__global__ void pack_bias(const float* __restrict__ bq, const float* __restrict__ bg,
                          float* __restrict__ bc) {
    int n = blockIdx.x * 256 + threadIdx.x;
    bc[n] = (n < 3072) ? bq[n] : bg[n - 3072];
}
__global__ void pack_wp(const float* __restrict__ wp, __half* __restrict__ wpT) {
    long long idx = (long long)blockIdx.x * 256 + threadIdx.x;
    int n = (int)(idx >> 10);
    int k = (int)(idx & 1023);
    wpT[idx] = __float2half_rn(wp[(long long)k * 1024 + n]);
}

// ---------------- zero Pk (accumulated by actT atomics) -----------------------
__global__ void zpk_kernel(float* __restrict__ pk) {
    pk[blockIdx.x * 256 + threadIdx.x] = 0.f;
}

// ---------------- fused activations + kv transpose + chunk K colsums ----------
__global__ void actT_kernel(__half* __restrict__ qkvh,
                            __half* __restrict__ kT, __half* __restrict__ vT,
                            float* __restrict__ pk) {
    __shared__ __half sk[64][65], sv[64][65];   // [d][t]
    __shared__ float ssum[8][64];
    int tx = threadIdx.x, ty = threadIdx.y;
    int t0 = blockIdx.x * 64, d0 = blockIdx.y * 64;
    float k0s = 0.f, k1s = 0.f;
#pragma unroll
    for (int i = 0; i < 8; i++) {
        int t = ty + i * 8;
        __half2* base = reinterpret_cast<__half2*>(qkvh + (long long)(t0 + t) * 4096);
        int dh = (d0 >> 1) + tx;
        __half2 qv = base[dh];
        __half2 kv = base[512 + dh];
        __half2 vv = base[1024 + dh];
        __half2 gv = base[1536 + dh];
        float q0 = __low2float(qv), q1 = __high2float(qv);
        float k0 = __low2float(kv), k1 = __high2float(kv);
        float g0 = __low2float(gv), g1 = __high2float(gv);
        float kg0 = k0 * __frcp_rn(1.f + __expf(-g0));
        float kg1 = k1 * __frcp_rn(1.f + __expf(-g1));
        q0  = (q0  > 0.f) ? (q0  + 1.f) : __expf(q0);
        q1  = (q1  > 0.f) ? (q1  + 1.f) : __expf(q1);
        kg0 = (kg0 > 0.f) ? (kg0 + 1.f) : __expf(kg0);
        kg1 = (kg1 > 0.f) ? (kg1 + 1.f) : __expf(kg1);
        __half2 qh = __floats2half2_rn(q0, q1);
        __half2 kh = __floats2half2_rn(kg0, kg1);
        base[dh] = qh;
        base[512 + dh] = kh;
        sk[2 * tx][t]     = __low2half(kh);
        sk[2 * tx + 1][t] = __high2half(kh);
        sv[2 * tx][t]     = __low2half(vv);
        sv[2 * tx + 1][t] = __high2half(vv);
        k0s += __half2float(__low2half(kh));
        k1s += __half2float(__high2half(kh));
    }
    ssum[ty][2 * tx]     = k0s;
    ssum[ty][2 * tx + 1] = k1s;
    __syncthreads();
    int tpair = t0 + 2 * tx;
    int b = tpair >> 12, t = tpair & 4095;
    int lt = 2 * tx;
#pragma unroll
    for (int i = 0; i < 8; i++) {
        int dd = ty + i * 8;
        int d = d0 + dd;
        long long o = ((long long)b * 1024 + d) * 4096 + t;
        *reinterpret_cast<__half2*>(kT + o) = __halves2half2(sk[dd][lt], sk[dd][lt + 1]);
        *reinterpret_cast<__half2*>(vT + o) = __halves2half2(sv[dd][lt], sv[dd][lt + 1]);
    }
    if (ty == 0) {
        float s0 = 0.f, s1 = 0.f;
#pragma unroll
        for (int j = 0; j < 8; j++) { s0 += ssum[j][tx]; s1 += ssum[j][tx + 32]; }
        int u = t0 >> 9;
        atomicAdd(&pk[u * D_MODEL + d0 + tx], s0);
        atomicAdd(&pk[u * D_MODEL + d0 + 32 + tx], s1);
    }
}

// ---------------- exclusive prefix over chunk planes (half2, in place) --------
#define PLANE2 524288   /* half2 elements per plane */
__global__ void prefix_p(__half2* __restrict__ P) {
    long long e = (long long)blockIdx.x * 256 + threadIdx.x;
    int b = (int)(e >> 19);
    long long off = e & (PLANE2 - 1);
    __half2* base = P + (long long)b * NCHUNK * PLANE2 + off;
    float r0 = 0.f, r1 = 0.f;
    __half2 nxt = base[0];
#pragma unroll
    for (int c = 1; c < NCHUNK; c++) {
        r0 += __low2float(nxt);
        r1 += __high2float(nxt);
        if (c < NCHUNK - 1) nxt = base[(long long)c * PLANE2];
        base[(long long)c * PLANE2] = __floats2half2_rn(r0, r1);
    }
}

__global__ void prefix_k(float* __restrict__ Pk) {
    int e = blockIdx.x * 256 + threadIdx.x;
    int b = e >> 10;
    int d = e & 1023;
    float* base = Pk + b * NCHUNK * D_MODEL + d;
    float run = 0.f;
#pragma unroll
    for (int c = 0; c < NCHUNK; c++) {
        float t = base[c * D_MODEL];
        base[c * D_MODEL] = run;
        run += t;
    }
}

// ---------------- den = eps + q . Sk (half2 reads) -----------------------------
__global__ void den_kernel(const __half* __restrict__ qkvh,
                           const float* __restrict__ pk,
                           float* __restrict__ den) {
    int warp = blockIdx.x * 8 + (threadIdx.x >> 5);
    int lane = threadIdx.x & 31;
    const __half2* q = reinterpret_cast<const __half2*>(qkvh + (long long)warp * 4096);
    const float* sk = pk + (warp / CHUNK) * D_MODEL;
    float s = 0.f;
#pragma unroll 4
    for (int i = lane; i < 512; i += 32) {
        __half2 v = q[i];
        s += __low2float(v) * sk[2 * i] + __high2float(v) * sk[2 * i + 1];
    }
#pragma unroll
    for (int o = 16; o > 0; o >>= 1) s += __shfl_xor_sync(0xffffffffu, s, o);
    if (lane == 0) den[warp] = s + DEN_EPS;
}

// ---------------- launch ------------------------------------------------------
extern "C" void kernel_launch(void* const* d_in, const int* in_sizes, int n_in,
                              void* d_out, int out_size) {
    const float* x      = (const float*)d_in[0];
    const float* w_qkv  = (const float*)d_in[1];
    const float* b_qkv  = (const float*)d_in[2];
    const float* w_gate = (const float*)d_in[3];
    const float* b_gate = (const float*)d_in[4];
    const float* w_proj = (const float*)d_in[5];
    const float* b_proj = (const float*)d_in[6];
    const float* ln_g   = (const float*)d_in[7];
    const float* ln_b   = (const float*)d_in[8];
    float* out = (float*)d_out;

    __half *p_xnh, *p_qkvh, *p_kT, *p_vT, *p_Ph, *p_attnh, *p_numh, *p_wth, *p_wph;
    float *p_Pk, *p_den, *p_bcat;
    cudaGetSymbolAddress((void**)&p_xnh,   g_xnh);
    cudaGetSymbolAddress((void**)&p_qkvh,  g_qkvh);
    cudaGetSymbolAddress((void**)&p_kT,    g_kT);
    cudaGetSymbolAddress((void**)&p_vT,    g_vT);
    cudaGetSymbolAddress((void**)&p_Ph,    g_Ph);
    cudaGetSymbolAddress((void**)&p_Pk,    g_Pk);
    cudaGetSymbolAddress((void**)&p_attnh, g_attnh);
    cudaGetSymbolAddress((void**)&p_numh,  g_numh);
    cudaGetSymbolAddress((void**)&p_den,   g_den);
    cudaGetSymbolAddress((void**)&p_wth,   g_wth);
    cudaGetSymbolAddress((void**)&p_wph,   g_wph);
    cudaGetSymbolAddress((void**)&p_bcat,  g_bcat);

    cudaFuncSetAttribute(pgemm<1>, cudaFuncAttributeMaxDynamicSharedMemorySize, SMEM_BYTES);
    cudaFuncSetAttribute(pgemm<5>, cudaFuncAttributeMaxDynamicSharedMemorySize, SMEM_BYTES);
    cudaFuncSetAttribute(hgemm<2>, cudaFuncAttributeMaxDynamicSharedMemorySize, SMEM_BYTES);
    cudaFuncSetAttribute(hgemm<3>, cudaFuncAttributeMaxDynamicSharedMemorySize, SMEM_BYTES);
    cudaFuncSetAttribute(num_kernel, cudaFuncAttributeMaxDynamicSharedMemorySize, SMEM_BYTES);

    // single stream; qkvg GEMM at launch index 3 for the ncu capture.
    ln_kernel<<<NROWS, 256>>>(x, ln_g, ln_b, p_xnh);                     // 0
    pack_w   <<<(4096 * 1024) / 256, 256>>>(w_qkv, w_gate, p_wth);       // 1
    pack_bias<<<4096 / 256, 256>>>(b_qkv, b_gate, p_bcat);               // 2

    // 3. qkvg = xn @ [w_qkv|w_gate] + bias -> qkvh fp16 (persistent GEMM)
    //    tiles: 128 m-blocks x 32 n-blocks = 4096; nxshift=5, nxmask=31
    pgemm<5><<<PGRID, 256, SMEM_BYTES>>>(
        p_xnh, 1024, p_wth, 1024, p_qkvh, 4096, p_bcat, 1024, 5, 31, 4096);

    pack_wp  <<<(1024 * 1024) / 256, 256>>>(w_proj, p_wph);              // 4
    zpk_kernel<<<(NUNITS * D_MODEL) / 256, 256>>>(p_Pk);                 // 5

    // 6. fused activations + kv transpose + chunk colsums
    actT_kernel<<<dim3(NROWS / 64, D_MODEL / 64), dim3(32, 8)>>>(p_qkvh, p_kT, p_vT, p_Pk);

    // 7. Pt_u = V_u^T @ K_u -> Ph planes (skip last chunk per batch)
    hgemm<2><<<dim3(8, 8, NUNITS), 256, SMEM_BYTES>>>(
        p_vT, 4096, 4194304LL, (long long)CHUNK,
        p_kT, 4096, 4194304LL, (long long)CHUNK,
        p_Ph, 1024, 1048576LL, nullptr, nullptr, CHUNK);

    // 8-9. exclusive prefix scans
    prefix_p<<<(B_SZ * PLANE2) / 256, 256>>>(reinterpret_cast<__half2*>(p_Ph));
    prefix_k<<<(B_SZ * D_MODEL) / 256, 256>>>(p_Pk);

    // 10. den = eps + q . Sk  (before attn atomics)
    den_kernel<<<NROWS / 8, 256>>>(p_qkvh, p_Pk, p_den);

    // 11. attn = tril(Q_u @ K_u^T) -> fp16 (10 tril blocks), rowsums -> den
    hgemm<3><<<dim3(10, 1, NUNITS), 256, SMEM_BYTES>>>(
        p_qkvh, 4096, (long long)NCHUNK * CHUNK * 4096, (long long)CHUNK * 4096,
        p_qkvh + 1024, 4096, (long long)NCHUNK * CHUNK * 4096, (long long)CHUNK * 4096,
        p_attnh, CHUNK, (long long)CHUNK * CHUNK, nullptr, p_den, 1024);

    // 12. num = (Q@S + attn@V) / den -> fp16
    num_kernel<<<dim3(8, 4, NUNITS), 256, SMEM_BYTES>>>(
        p_qkvh, p_Ph, p_attnh, p_vT, p_den, p_numh);

    // 13. out = numh @ w_proj + b_proj  (persistent GEMM, 128x8 = 1024 tiles)
    pgemm<1><<<PGRID, 256, SMEM_BYTES>>>(
        p_numh, 1024, p_wph, 1024, out, 1024, b_proj, 1024, 3, 7, 1024);
}

// round 16
// speedup vs baseline: 1.0523x; 1.0523x over previous
#include <cuda_runtime.h>
#include <cuda_fp16.h>
#include <cstdint>
#include <math.h>

#define D_MODEL 1024
#define B_SZ 4
#define T_SZ 4096
#define NROWS (B_SZ * T_SZ)          /* 16384 */
#define CHUNK 512
#define NCHUNK (T_SZ / CHUNK)        /* 8 */
#define NUNITS (B_SZ * NCHUNK)       /* 32 */
#define LN_EPS 1e-5f
#define DEN_EPS 1e-6f

// ---------------- scratch (device globals; no allocations allowed) -----------
__device__ __half g_xnh[(size_t)NROWS * D_MODEL];
__device__ __half g_qkvh[(size_t)NROWS * 4 * D_MODEL];
__device__ __half g_kT[(size_t)B_SZ * D_MODEL * T_SZ];
__device__ __half g_vT[(size_t)B_SZ * D_MODEL * T_SZ];
__device__ __half g_Ph[(size_t)NUNITS * D_MODEL * D_MODEL];
__device__ float  g_Pk[NUNITS * D_MODEL];
__device__ __half g_attnh[(size_t)NUNITS * CHUNK * CHUNK];
__device__ __half g_numh[(size_t)NROWS * D_MODEL];
__device__ float  g_den[NROWS];
__device__ __half g_wth[(size_t)4096 * 1024];
__device__ __half g_wph[(size_t)1024 * 1024];
__device__ float  g_bcat[4096];

// tril block map for 512x512 attn tile (10 blocks of 128x128)
__constant__ int c_bm[10] = {0, 1, 1, 2, 2, 2, 3, 3, 3, 3};
__constant__ int c_bn[10] = {0, 0, 1, 0, 1, 2, 0, 1, 2, 3};

// ---------------- helpers -----------------------------------------------------
__device__ __forceinline__ uint32_t smem_u32(const void* p) {
    uint32_t a;
    asm("{ .reg .u64 t; cvta.to.shared.u64 t, %1; cvt.u32.u64 %0, t; }" : "=r"(a) : "l"(p));
    return a;
}

#define CP16(dst, src) \
    asm volatile("cp.async.cg.shared.global [%0], [%1], 16;" :: "r"(dst), "l"(src))
#define CP_COMMIT() asm volatile("cp.async.commit_group;" ::: "memory")
#define CP_WAIT(n)  asm volatile("cp.async.wait_group %0;" :: "n"(n) : "memory")

#define LDM4(r0, r1, r2, r3, addr) \
    asm volatile("ldmatrix.sync.aligned.m8n8.x4.shared.b16 {%0,%1,%2,%3}, [%4];" \
                 : "=r"(r0), "=r"(r1), "=r"(r2), "=r"(r3) : "r"(addr))

#define MMA16(c, a, b) \
    asm volatile( \
        "mma.sync.aligned.m16n8k16.row.col.f32.f16.f16.f32 " \
        "{%0,%1,%2,%3}, {%4,%5,%6,%7}, {%8,%9}, {%0,%1,%2,%3};" \
        : "+f"((c)[0]), "+f"((c)[1]), "+f"((c)[2]), "+f"((c)[3]) \
        : "r"((a)[0]), "r"((a)[1]), "r"((a)[2]), "r"((a)[3]), \
          "r"((b)[0]), "r"((b)[1]))

#define STB 32768                   /* stage bytes: A 16KB + B 16KB */
#define SMEM_BYTES (3 * STB)        /* 98304 */

// Common warp/fragment indexing for the 128x128 tile, 8 warps (2M x 4N)
struct TileIdx {
    int lane, w, wm, wn, g, lr, l4q, lmq, cxA, cxB;
    int rA[4], rB[2];
    __device__ __forceinline__ TileIdx(int tid) {
        lane = tid & 31; w = tid >> 5;
        wm = (w & 1) * 64; wn = (w >> 1) * 32;
        g = lane >> 3; lr = lane & 7;
        l4q = lane >> 2; lmq = lane & 3;
        cxA = (g >> 1); cxB = (g & 1);
#pragma unroll
        for (int mt = 0; mt < 4; mt++) rA[mt] = (wm + mt * 16 + lr + 8 * (g & 1)) * 128;
#pragma unroll
        for (int p = 0; p < 2; p++) rB[p] = (wn + p * 16 + lr + 8 * (g >> 1)) * 128;
    }
};

// ---------------- fp16 tensor-core GEMM ---------------------------------------
// EPI: 1 bias+f32 out, 2 half out (P GEMM; skip last chunk), 3 tril-mapped
//      attn: mask+half out+rowsum->den, 5 bias+half out.
template <int EPI>
__global__ void __launch_bounds__(256, 2) hgemm(
    const __half* __restrict__ A, int lda, long long sAb, long long sAc,
    const __half* __restrict__ B, int ldb, long long sBb, long long sBc,
    void* __restrict__ C, int ldc, long long sC,
    const float* __restrict__ bias, float* __restrict__ den, int K) {
    extern __shared__ char sm[];
    const uint32_t su = smem_u32(sm);
    const int tid = threadIdx.x;
    const int u = blockIdx.z;
    const int ub = u >> 3, uc = u & 7;

    if (EPI == 2 && uc == NCHUNK - 1) return;   // last chunk's P never consumed

    const __half* Ab = A + ub * sAb + uc * sAc;
    const __half* Bb = B + ub * sBb + uc * sBc;
    int m0, n0;
    if (EPI == 3) { m0 = c_bm[blockIdx.x] * 128; n0 = c_bn[blockIdx.x] * 128; }
    else          { m0 = blockIdx.y * 128;       n0 = blockIdx.x * 128; }

    const TileIdx ti(tid);

    auto loadA = [&](int st, int kt) {
        uint32_t dst = su + st * STB;
        int k0 = kt * 64;
#pragma unroll
        for (int p = 0; p < 4; p++) {
            int c = tid + p * 256;
            int row = c >> 3, ch = c & 7;
            const __half* src = Ab + (long long)(m0 + row) * lda + k0 + ch * 8;
            CP16(dst + row * 128 + ((ch ^ (row & 7)) << 4), src);
        }
    };
    auto loadB = [&](int st, int kt) {
        uint32_t dst = su + st * STB + 16384;
        int k0 = kt * 64;
#pragma unroll
        for (int p = 0; p < 4; p++) {
            int c = tid + p * 256;
            int row = c >> 3, ch = c & 7;
            const __half* src = Bb + (long long)(n0 + row) * ldb + k0 + ch * 8;
            CP16(dst + row * 128 + ((ch ^ (row & 7)) << 4), src);
        }
    };

    float acc[4][4][4];
#pragma unroll
    for (int mt = 0; mt < 4; mt++)
#pragma unroll
        for (int nt = 0; nt < 4; nt++)
#pragma unroll
            for (int r = 0; r < 4; r++) acc[mt][nt][r] = 0.f;

    const int KT = K >> 6;
    loadA(0, 0); loadB(0, 0); CP_COMMIT();
    if (KT > 1) { loadA(1, 1); loadB(1, 1); CP_COMMIT(); }

    int st = 0, stn = 2;
    for (int i = 0; i < KT; i++) {
        if (i < KT - 1) { CP_WAIT(1); } else { CP_WAIT(0); }
        __syncthreads();
        if (i + 2 < KT) {
            loadA(stn, i + 2); loadB(stn, i + 2); CP_COMMIT();
            stn = (stn == 2) ? 0 : stn + 1;
        }
        uint32_t Abase = su + st * STB;
        uint32_t Bbase = Abase + 16384;
        st = (st == 2) ? 0 : st + 1;
#pragma unroll
        for (int kk = 0; kk < 4; kk++) {
            uint32_t af[4][4], bf[4][2];
            int cA = ((kk * 2 + ti.cxA) ^ ti.lr) << 4;
            int cB = ((kk * 2 + ti.cxB) ^ ti.lr) << 4;
#pragma unroll
            for (int mt = 0; mt < 4; mt++)
                LDM4(af[mt][0], af[mt][1], af[mt][2], af[mt][3], Abase + ti.rA[mt] + cA);
            LDM4(bf[0][0], bf[0][1], bf[1][0], bf[1][1], Bbase + ti.rB[0] + cB);
            LDM4(bf[2][0], bf[2][1], bf[3][0], bf[3][1], Bbase + ti.rB[1] + cB);
#pragma unroll
            for (int mt = 0; mt < 4; mt++)
#pragma unroll
                for (int nt = 0; nt < 4; nt++)
                    MMA16(acc[mt][nt], af[mt], bf[nt]);
        }
    }

    // ---- epilogue ----
    float* Cf = (float*)C + (long long)u * sC;
    __half* Ch = (__half*)C + (long long)u * sC;

#pragma unroll
    for (int mt = 0; mt < 4; mt++) {
        int row0 = m0 + ti.wm + mt * 16 + ti.l4q;
        int row1 = row0 + 8;
        float rs0 = 0.f, rs1 = 0.f;
#pragma unroll
        for (int nt = 0; nt < 4; nt++) {
            int col = n0 + ti.wn + nt * 8 + ti.lmq * 2;
            float v0 = acc[mt][nt][0], v1 = acc[mt][nt][1];
            float v2 = acc[mt][nt][2], v3 = acc[mt][nt][3];
            if (EPI == 1 || EPI == 5) {
                float b0 = bias[col], b1 = bias[col + 1];
                v0 += b0; v1 += b1; v2 += b0; v3 += b1;
            }
            if (EPI == 3) {
                v0 = (col     > row0) ? 0.f : v0;
                v1 = (col + 1 > row0) ? 0.f : v1;
                v2 = (col     > row1) ? 0.f : v2;
                v3 = (col + 1 > row1) ? 0.f : v3;
            }
            if (EPI == 1) {
                *reinterpret_cast<float2*>(Cf + (long long)row0 * ldc + col) = make_float2(v0, v1);
                *reinterpret_cast<float2*>(Cf + (long long)row1 * ldc + col) = make_float2(v2, v3);
            } else {
                __half2 h0 = __floats2half2_rn(v0, v1);
                __half2 h1 = __floats2half2_rn(v2, v3);
                if (EPI == 3) {
                    rs0 += __half2float(h0.x) + __half2float(h0.y);
                    rs1 += __half2float(h1.x) + __half2float(h1.y);
                }
                *reinterpret_cast<__half2*>(Ch + (long long)row0 * ldc + col) = h0;
                *reinterpret_cast<__half2*>(Ch + (long long)row1 * ldc + col) = h1;
            }
        }
        if (EPI == 3) {
            rs0 += __shfl_xor_sync(0xffffffffu, rs0, 1);
            rs0 += __shfl_xor_sync(0xffffffffu, rs0, 2);
            rs1 += __shfl_xor_sync(0xffffffffu, rs1, 1);
            rs1 += __shfl_xor_sync(0xffffffffu, rs1, 2);
            if (ti.lmq == 0) {
                atomicAdd(den + (long long)u * CHUNK + row0, rs0);
                atomicAdd(den + (long long)u * CHUNK + row1, rs1);
            }
        }
    }
}

// ---------------- fused num kernel: num = (Q@S + attn@V) / den -> fp16 --------
__global__ void __launch_bounds__(256, 2) num_kernel(
    const __half* __restrict__ qkvh, const __half* __restrict__ Ph,
    const __half* __restrict__ attnh, const __half* __restrict__ vT,
    const float* __restrict__ den, __half* __restrict__ numh) {
    extern __shared__ char sm[];
    const uint32_t su = smem_u32(sm);
    const int tid = threadIdx.x;
    const int u = blockIdx.z;
    const int ub = u >> 3, uc = u & 7;
    const int m0 = blockIdx.y * 128;
    const int n0 = blockIdx.x * 128;
    const TileIdx ti(tid);

    float acc[4][4][4];
#pragma unroll
    for (int mt = 0; mt < 4; mt++)
#pragma unroll
        for (int nt = 0; nt < 4; nt++)
#pragma unroll
            for (int r = 0; r < 4; r++) acc[mt][nt][r] = 0.f;

    auto phase = [&](const __half* Ab, int lda, const __half* Bb, int ldb, int KT) {
        __syncthreads();   // stage-reuse guard at phase boundary
        auto loadA = [&](int st, int kt) {
            uint32_t dst = su + st * STB;
            int k0 = kt * 64;
#pragma unroll
            for (int p = 0; p < 4; p++) {
                int c = tid + p * 256;
                int row = c >> 3, ch = c & 7;
                const __half* src = Ab + (long long)(m0 + row) * lda + k0 + ch * 8;
                CP16(dst + row * 128 + ((ch ^ (row & 7)) << 4), src);
            }
        };
        auto loadB = [&](int st, int kt) {
            uint32_t dst = su + st * STB + 16384;
            int k0 = kt * 64;
#pragma unroll
            for (int p = 0; p < 4; p++) {
                int c = tid + p * 256;
                int row = c >> 3, ch = c & 7;
                const __half* src = Bb + (long long)(n0 + row) * ldb + k0 + ch * 8;
                CP16(dst + row * 128 + ((ch ^ (row & 7)) << 4), src);
            }
        };
        loadA(0, 0); loadB(0, 0); CP_COMMIT();
        if (KT > 1) { loadA(1, 1); loadB(1, 1); CP_COMMIT(); }
        int st = 0, stn = 2;
        for (int i = 0; i < KT; i++) {
            if (i < KT - 1) { CP_WAIT(1); } else { CP_WAIT(0); }
            __syncthreads();
            if (i + 2 < KT) {
                loadA(stn, i + 2); loadB(stn, i + 2); CP_COMMIT();
                stn = (stn == 2) ? 0 : stn + 1;
            }
            uint32_t Abase = su + st * STB;
            uint32_t Bbase = Abase + 16384;
            st = (st == 2) ? 0 : st + 1;
#pragma unroll
            for (int kk = 0; kk < 4; kk++) {
                uint32_t af[4][4], bf[4][2];
                int cA = ((kk * 2 + ti.cxA) ^ ti.lr) << 4;
                int cB = ((kk * 2 + ti.cxB) ^ ti.lr) << 4;
#pragma unroll
                for (int mt = 0; mt < 4; mt++)
                    LDM4(af[mt][0], af[mt][1], af[mt][2], af[mt][3], Abase + ti.rA[mt] + cA);
                LDM4(bf[0][0], bf[0][1], bf[1][0], bf[1][1], Bbase + ti.rB[0] + cB);
                LDM4(bf[2][0], bf[2][1], bf[3][0], bf[3][1], Bbase + ti.rB[1] + cB);
#pragma unroll
                for (int mt = 0; mt < 4; mt++)
#pragma unroll
                    for (int nt = 0; nt < 4; nt++)
                        MMA16(acc[mt][nt], af[mt], bf[nt]);
            }
        }
    };

    // Phase 1: Q @ S   (S_0 = 0 -> skip for first chunk of each batch)
    if (uc != 0)
        phase(qkvh + (long long)u * CHUNK * 4096, 4096,
              Ph + (long long)u * 1048576, 1024, 16);
    // Phase 2: attn @ V  (causal-truncated K)
    int K2 = m0 + 128;
    phase(attnh + (long long)u * CHUNK * CHUNK, CHUNK,
          vT + (long long)ub * 4194304 + uc * CHUNK, 4096, K2 >> 6);

    // epilogue: / den -> fp16
    __half* Ch = numh + (long long)u * CHUNK * 1024;
#pragma unroll
    for (int mt = 0; mt < 4; mt++) {
        int row0 = m0 + ti.wm + mt * 16 + ti.l4q;
        int row1 = row0 + 8;
        float rcp0 = __frcp_rn(den[(long long)u * CHUNK + row0]);
        float rcp1 = __frcp_rn(den[(long long)u * CHUNK + row1]);
#pragma unroll
        for (int nt = 0; nt < 4; nt++) {
            int col = n0 + ti.wn + nt * 8 + ti.lmq * 2;
            __half2 h0 = __floats2half2_rn(acc[mt][nt][0] * rcp0, acc[mt][nt][1] * rcp0);
            __half2 h1 = __floats2half2_rn(acc[mt][nt][2] * rcp1, acc[mt][nt][3] * rcp1);
            *reinterpret_cast<__half2*>(Ch + (long long)row0 * 1024 + col) = h0;
            *reinterpret_cast<__half2*>(Ch + (long long)row1 * 1024 + col) = h1;
        }
    }
}

// ---------------- LayerNorm -> fp16 -------------------------------------------
__global__ void ln_kernel(const float* __restrict__ x,
                          const float* __restrict__ g,
                          const float* __restrict__ b,
                          __half* __restrict__ xn) {
    int row = blockIdx.x;
    const float* xr = x + (size_t)row * D_MODEL;
    __half* outr = xn + (size_t)row * D_MODEL;
    int tid = threadIdx.x;
    float vals[4];
    float s = 0.f, ss = 0.f;
#pragma unroll
    for (int i = 0; i < 4; i++) {
        float v = xr[tid + i * 256];
        vals[i] = v; s += v; ss += v * v;
    }
#pragma unroll
    for (int o = 16; o > 0; o >>= 1) {
        s  += __shfl_xor_sync(0xffffffffu, s, o);
        ss += __shfl_xor_sync(0xffffffffu, ss, o);
    }
    __shared__ float sbuf[8], ssbuf[8];
    int warp = tid >> 5, lane = tid & 31;
    if (lane == 0) { sbuf[warp] = s; ssbuf[warp] = ss; }
    __syncthreads();
    float ts = 0.f, tss = 0.f;
#pragma unroll
    for (int wq = 0; wq < 8; wq++) { ts += sbuf[wq]; tss += ssbuf[wq]; }
    float mu = ts * (1.0f / D_MODEL);
    float var = tss * (1.0f / D_MODEL) - mu * mu;
    float inv = rsqrtf(var + LN_EPS);
#pragma unroll
    for (int i = 0; i < 4; i++) {
        int d = tid + i * 256;
        outr[d] = __float2half_rn((vals[i] - mu) * inv * g[d] + b[d]);
    }
}

// ---------------- fused prepack: wt | wpT | bias | zero Pk --------------------
#define PK_N1 (4096LL * 1024)
#define PK_N2 (PK_N1 + 1024LL * 1024)
#define PK_N3 (PK_N2 + 4096)
#define PK_N4 (PK_N3 + (long long)NUNITS * D_MODEL)
__global__ void pack_all(const float* __restrict__ wq, const float* __restrict__ wg,
                         const float* __restrict__ wp,
                         const float* __restrict__ bq, const float* __restrict__ bg,
                         __half* __restrict__ wt, __half* __restrict__ wpT,
                         float* __restrict__ bc, float* __restrict__ pk) {
    long long idx = (long long)blockIdx.x * 256 + threadIdx.x;
    if (idx < PK_N1) {
        int n = (int)(idx >> 10);
        int k = (int)(idx & 1023);
        float v = (n < 3072) ? wq[(long long)k * 3072 + n] : wg[(long long)k * 1024 + n - 3072];
        wt[idx] = __float2half_rn(v);
    } else if (idx < PK_N2) {
        long long e = idx - PK_N1;
        int n = (int)(e >> 10);
        int k = (int)(e & 1023);
        wpT[e] = __float2half_rn(wp[(long long)k * 1024 + n]);
    } else if (idx < PK_N3) {
        int n = (int)(idx - PK_N2);
        bc[n] = (n < 3072) ? bq[n] : bg[n - 3072];
    } else if (idx < PK_N4) {
        pk[idx - PK_N3] = 0.f;
    }
}

// ---------------- fused activations + kv transpose + chunk K colsums ----------
__global__ void actT_kernel(__half* __restrict__ qkvh,
                            __half* __restrict__ kT, __half* __restrict__ vT,
                            float* __restrict__ pk) {
    __shared__ __half sk[64][65], sv[64][65];   // [d][t]
    __shared__ float ssum[8][64];
    int tx = threadIdx.x, ty = threadIdx.y;
    int t0 = blockIdx.x * 64, d0 = blockIdx.y * 64;
    float k0s = 0.f, k1s = 0.f;
#pragma unroll
    for (int i = 0; i < 8; i++) {
        int t = ty + i * 8;
        __half2* base = reinterpret_cast<__half2*>(qkvh + (long long)(t0 + t) * 4096);
        int dh = (d0 >> 1) + tx;
        __half2 qv = base[dh];
        __half2 kv = base[512 + dh];
        __half2 vv = base[1024 + dh];
        __half2 gv = base[1536 + dh];
        float q0 = __low2float(qv), q1 = __high2float(qv);
        float k0 = __low2float(kv), k1 = __high2float(kv);
        float g0 = __low2float(gv), g1 = __high2float(gv);
        float kg0 = k0 * __frcp_rn(1.f + __expf(-g0));
        float kg1 = k1 * __frcp_rn(1.f + __expf(-g1));
        q0  = (q0  > 0.f) ? (q0  + 1.f) : __expf(q0);
        q1  = (q1  > 0.f) ? (q1  + 1.f) : __expf(q1);
        kg0 = (kg0 > 0.f) ? (kg0 + 1.f) : __expf(kg0);
        kg1 = (kg1 > 0.f) ? (kg1 + 1.f) : __expf(kg1);
        __half2 qh = __floats2half2_rn(q0, q1);
        __half2 kh = __floats2half2_rn(kg0, kg1);
        base[dh] = qh;
        base[512 + dh] = kh;
        sk[2 * tx][t]     = __low2half(kh);
        sk[2 * tx + 1][t] = __high2half(kh);
        sv[2 * tx][t]     = __low2half(vv);
        sv[2 * tx + 1][t] = __high2half(vv);
        k0s += __half2float(__low2half(kh));
        k1s += __half2float(__high2half(kh));
    }
    ssum[ty][2 * tx]     = k0s;
    ssum[ty][2 * tx + 1] = k1s;
    __syncthreads();
    int tpair = t0 + 2 * tx;
    int b = tpair >> 12, t = tpair & 4095;
    int lt = 2 * tx;
#pragma unroll
    for (int i = 0; i < 8; i++) {
        int dd = ty + i * 8;
        int d = d0 + dd;
        long long o = ((long long)b * 1024 + d) * 4096 + t;
        *reinterpret_cast<__half2*>(kT + o) = __halves2half2(sk[dd][lt], sk[dd][lt + 1]);
        *reinterpret_cast<__half2*>(vT + o) = __halves2half2(sv[dd][lt], sv[dd][lt + 1]);
    }
    if (ty == 0) {
        float s0 = 0.f, s1 = 0.f;
#pragma unroll
        for (int j = 0; j < 8; j++) { s0 += ssum[j][tx]; s1 += ssum[j][tx + 32]; }
        int u = t0 >> 9;
        atomicAdd(&pk[u * D_MODEL + d0 + tx], s0);
        atomicAdd(&pk[u * D_MODEL + d0 + 32 + tx], s1);
    }
}

// ---------------- exclusive prefix over chunk planes (half2, in place) --------
#define PLANE2 524288   /* half2 elements per plane */
__global__ void prefix_p(__half2* __restrict__ P) {
    long long e = (long long)blockIdx.x * 256 + threadIdx.x;
    int b = (int)(e >> 19);
    long long off = e & (PLANE2 - 1);
    __half2* base = P + (long long)b * NCHUNK * PLANE2 + off;
    float r0 = 0.f, r1 = 0.f;
    __half2 nxt = base[0];
#pragma unroll
    for (int c = 1; c < NCHUNK; c++) {
        r0 += __low2float(nxt);
        r1 += __high2float(nxt);
        if (c < NCHUNK - 1) nxt = base[(long long)c * PLANE2];
        base[(long long)c * PLANE2] = __floats2half2_rn(r0, r1);
    }
}

__global__ void prefix_k(float* __restrict__ Pk) {
    int e = blockIdx.x * 256 + threadIdx.x;
    int b = e >> 10;
    int d = e & 1023;
    float* base = Pk + b * NCHUNK * D_MODEL + d;
    float run = 0.f;
#pragma unroll
    for (int c = 0; c < NCHUNK; c++) {
        float t = base[c * D_MODEL];
        base[c * D_MODEL] = run;
        run += t;
    }
}

// ---------------- den = eps + q . Sk (half2 reads) -----------------------------
__global__ void den_kernel(const __half* __restrict__ qkvh,
                           const float* __restrict__ pk,
                           float* __restrict__ den) {
    int warp = blockIdx.x * 8 + (threadIdx.x >> 5);
    int lane = threadIdx.x & 31;
    const __half2* q = reinterpret_cast<const __half2*>(qkvh + (long long)warp * 4096);
    const float* sk = pk + (warp / CHUNK) * D_MODEL;
    float s = 0.f;
#pragma unroll 4
    for (int i = lane; i < 512; i += 32) {
        __half2 v = q[i];
        s += __low2float(v) * sk[2 * i] + __high2float(v) * sk[2 * i + 1];
    }
#pragma unroll
    for (int o = 16; o > 0; o >>= 1) s += __shfl_xor_sync(0xffffffffu, s, o);
    if (lane == 0) den[warp] = s + DEN_EPS;
}

// ---------------- launch ------------------------------------------------------
extern "C" void kernel_launch(void* const* d_in, const int* in_sizes, int n_in,
                              void* d_out, int out_size) {
    const float* x      = (const float*)d_in[0];
    const float* w_qkv  = (const float*)d_in[1];
    const float* b_qkv  = (const float*)d_in[2];
    const float* w_gate = (const float*)d_in[3];
    const float* b_gate = (const float*)d_in[4];
    const float* w_proj = (const float*)d_in[5];
    const float* b_proj = (const float*)d_in[6];
    const float* ln_g   = (const float*)d_in[7];
    const float* ln_b   = (const float*)d_in[8];
    float* out = (float*)d_out;

    __half *p_xnh, *p_qkvh, *p_kT, *p_vT, *p_Ph, *p_attnh, *p_numh, *p_wth, *p_wph;
    float *p_Pk, *p_den, *p_bcat;
    cudaGetSymbolAddress((void**)&p_xnh,   g_xnh);
    cudaGetSymbolAddress((void**)&p_qkvh,  g_qkvh);
    cudaGetSymbolAddress((void**)&p_kT,    g_kT);
    cudaGetSymbolAddress((void**)&p_vT,    g_vT);
    cudaGetSymbolAddress((void**)&p_Ph,    g_Ph);
    cudaGetSymbolAddress((void**)&p_Pk,    g_Pk);
    cudaGetSymbolAddress((void**)&p_attnh, g_attnh);
    cudaGetSymbolAddress((void**)&p_numh,  g_numh);
    cudaGetSymbolAddress((void**)&p_den,   g_den);
    cudaGetSymbolAddress((void**)&p_wth,   g_wth);
    cudaGetSymbolAddress((void**)&p_wph,   g_wph);
    cudaGetSymbolAddress((void**)&p_bcat,  g_bcat);

    cudaFuncSetAttribute(hgemm<1>, cudaFuncAttributeMaxDynamicSharedMemorySize, SMEM_BYTES);
    cudaFuncSetAttribute(hgemm<2>, cudaFuncAttributeMaxDynamicSharedMemorySize, SMEM_BYTES);
    cudaFuncSetAttribute(hgemm<3>, cudaFuncAttributeMaxDynamicSharedMemorySize, SMEM_BYTES);
    cudaFuncSetAttribute(hgemm<5>, cudaFuncAttributeMaxDynamicSharedMemorySize, SMEM_BYTES);
    cudaFuncSetAttribute(num_kernel, cudaFuncAttributeMaxDynamicSharedMemorySize, SMEM_BYTES);

    // single stream; qkvg GEMM at launch index 2.
    ln_kernel<<<NROWS, 256>>>(x, ln_g, ln_b, p_xnh);                     // 0
    pack_all<<<(int)((PK_N4 + 255) / 256), 256>>>(w_qkv, w_gate, w_proj,
                                                  b_qkv, b_gate,
                                                  p_wth, p_wph, p_bcat, p_Pk);  // 1

    // 2. qkvg = xn @ [w_qkv|w_gate] + bias  -> qkvh fp16
    hgemm<5><<<dim3(32, 128, 1), 256, SMEM_BYTES>>>(
        p_xnh, 1024, 0, 0, p_wth, 1024, 0, 0,
        p_qkvh, 4096, 0, p_bcat, nullptr, 1024);

    // 3. fused activations + kv transpose + chunk colsums (half2, fast-math)
    actT_kernel<<<dim3(NROWS / 64, D_MODEL / 64), dim3(32, 8)>>>(p_qkvh, p_kT, p_vT, p_Pk);

    // 4. Pt_u = V_u^T @ K_u -> Ph planes (skip last chunk per batch)
    hgemm<2><<<dim3(8, 8, NUNITS), 256, SMEM_BYTES>>>(
        p_vT, 4096, 4194304LL, (long long)CHUNK,
        p_kT, 4096, 4194304LL, (long long)CHUNK,
        p_Ph, 1024, 1048576LL, nullptr, nullptr, CHUNK);

    // 5-6. exclusive prefix scans
    prefix_p<<<(B_SZ * PLANE2) / 256, 256>>>(reinterpret_cast<__half2*>(p_Ph));
    prefix_k<<<(B_SZ * D_MODEL) / 256, 256>>>(p_Pk);

    // 7. den = eps + q . Sk  (before attn atomics)
    den_kernel<<<NROWS / 8, 256>>>(p_qkvh, p_Pk, p_den);

    // 8. attn = tril(Q_u @ K_u^T) -> fp16 (10 tril blocks), rowsums -> den
    hgemm<3><<<dim3(10, 1, NUNITS), 256, SMEM_BYTES>>>(
        p_qkvh, 4096, (long long)NCHUNK * CHUNK * 4096, (long long)CHUNK * 4096,
        p_qkvh + 1024, 4096, (long long)NCHUNK * CHUNK * 4096, (long long)CHUNK * 4096,
        p_attnh, CHUNK, (long long)CHUNK * CHUNK, nullptr, p_den, 1024);

    // 9. num = (Q@S + attn@V) / den -> fp16
    num_kernel<<<dim3(8, 4, NUNITS), 256, SMEM_BYTES>>>(
        p_qkvh, p_Ph, p_attnh, p_vT, p_den, p_numh);

    // 10. out = numh @ w_proj + b_proj
    hgemm<1><<<dim3(8, 128, 1), 256, SMEM_BYTES>>>(
        p_numh, 1024, 0, 0, p_wph, 1024, 0, 0,
        out, 1024, 0, b_proj, nullptr, 1024);
}

// round 17
// speedup vs baseline: 1.0747x; 1.0212x over previous
#include <cuda_runtime.h>
#include <cuda_fp16.h>
#include <cstdint>
#include <math.h>

#define D_MODEL 1024
#define B_SZ 4
#define T_SZ 4096
#define NROWS (B_SZ * T_SZ)          /* 16384 */
#define CHUNK 512
#define NCHUNK (T_SZ / CHUNK)        /* 8 */
#define NUNITS (B_SZ * NCHUNK)       /* 32 */
#define LN_EPS 1e-5f
#define DEN_EPS 1e-6f

// ---------------- scratch (device globals; no allocations allowed) -----------
__device__ __half g_xnh[(size_t)NROWS * D_MODEL];
__device__ __half g_qkvh[(size_t)NROWS * 4 * D_MODEL];
__device__ __half g_kT[(size_t)B_SZ * D_MODEL * T_SZ];
__device__ __half g_vT[(size_t)B_SZ * D_MODEL * T_SZ];
__device__ __half g_Ph[(size_t)NUNITS * D_MODEL * D_MODEL];
__device__ float  g_Pk[NUNITS * D_MODEL];
__device__ __half g_attnh[(size_t)NUNITS * CHUNK * CHUNK];
__device__ __half g_numh[(size_t)NROWS * D_MODEL];
__device__ float  g_den[NROWS];
__device__ __half g_wth[(size_t)4096 * 1024];
__device__ __half g_wph[(size_t)1024 * 1024];
__device__ float  g_bcat[4096];

// tril block map for 512x512 attn tile (10 blocks of 128x128)
__constant__ int c_bm[10] = {0, 1, 1, 2, 2, 2, 3, 3, 3, 3};
__constant__ int c_bn[10] = {0, 0, 1, 0, 1, 2, 0, 1, 2, 3};

// ---------------- helpers -----------------------------------------------------
__device__ __forceinline__ uint32_t smem_u32(const void* p) {
    uint32_t a;
    asm("{ .reg .u64 t; cvta.to.shared.u64 t, %1; cvt.u32.u64 %0, t; }" : "=r"(a) : "l"(p));
    return a;
}

#define CP16(dst, src) \
    asm volatile("cp.async.cg.shared.global [%0], [%1], 16;" :: "r"(dst), "l"(src))
#define CP_COMMIT() asm volatile("cp.async.commit_group;" ::: "memory")
#define CP_WAIT(n)  asm volatile("cp.async.wait_group %0;" :: "n"(n) : "memory")

#define LDM4(r0, r1, r2, r3, addr) \
    asm volatile("ldmatrix.sync.aligned.m8n8.x4.shared.b16 {%0,%1,%2,%3}, [%4];" \
                 : "=r"(r0), "=r"(r1), "=r"(r2), "=r"(r3) : "r"(addr))

#define MMA16(c, a, b) \
    asm volatile( \
        "mma.sync.aligned.m16n8k16.row.col.f32.f16.f16.f32 " \
        "{%0,%1,%2,%3}, {%4,%5,%6,%7}, {%8,%9}, {%0,%1,%2,%3};" \
        : "+f"((c)[0]), "+f"((c)[1]), "+f"((c)[2]), "+f"((c)[3]) \
        : "r"((a)[0]), "r"((a)[1]), "r"((a)[2]), "r"((a)[3]), \
          "r"((b)[0]), "r"((b)[1]))

#define STB 32768                   /* stage bytes: A 16KB + B 16KB */
#define SMEM_BYTES (3 * STB)        /* 98304 */

// Common warp/fragment indexing for the 128x128 tile, 8 warps (2M x 4N)
struct TileIdx {
    int lane, w, wm, wn, g, lr, l4q, lmq, cxA, cxB;
    int rA[4], rB[2];
    __device__ __forceinline__ TileIdx(int tid) {
        lane = tid & 31; w = tid >> 5;
        wm = (w & 1) * 64; wn = (w >> 1) * 32;
        g = lane >> 3; lr = lane & 7;
        l4q = lane >> 2; lmq = lane & 3;
        cxA = (g >> 1); cxB = (g & 1);
#pragma unroll
        for (int mt = 0; mt < 4; mt++) rA[mt] = (wm + mt * 16 + lr + 8 * (g & 1)) * 128;
#pragma unroll
        for (int p = 0; p < 2; p++) rB[p] = (wn + p * 16 + lr + 8 * (g >> 1)) * 128;
    }
};

// ---------------- fp16 tensor-core GEMM (standalone; EPI 1,5) -----------------
// EPI: 1 bias+f32 out, 5 bias+half out.
template <int EPI>
__global__ void __launch_bounds__(256, 2) hgemm(
    const __half* __restrict__ A, int lda,
    const __half* __restrict__ B, int ldb,
    void* __restrict__ C, int ldc,
    const float* __restrict__ bias, int K) {
    extern __shared__ char sm[];
    const uint32_t su = smem_u32(sm);
    const int tid = threadIdx.x;
    const int m0 = blockIdx.y * 128;
    const int n0 = blockIdx.x * 128;
    const TileIdx ti(tid);

    auto loadA = [&](int st, int kt) {
        uint32_t dst = su + st * STB;
        int k0 = kt * 64;
#pragma unroll
        for (int p = 0; p < 4; p++) {
            int c = tid + p * 256;
            int row = c >> 3, ch = c & 7;
            CP16(dst + row * 128 + ((ch ^ (row & 7)) << 4),
                 A + (long long)(m0 + row) * lda + k0 + ch * 8);
        }
    };
    auto loadB = [&](int st, int kt) {
        uint32_t dst = su + st * STB + 16384;
        int k0 = kt * 64;
#pragma unroll
        for (int p = 0; p < 4; p++) {
            int c = tid + p * 256;
            int row = c >> 3, ch = c & 7;
            CP16(dst + row * 128 + ((ch ^ (row & 7)) << 4),
                 B + (long long)(n0 + row) * ldb + k0 + ch * 8);
        }
    };

    float acc[4][4][4];
#pragma unroll
    for (int mt = 0; mt < 4; mt++)
#pragma unroll
        for (int nt = 0; nt < 4; nt++)
#pragma unroll
            for (int r = 0; r < 4; r++) acc[mt][nt][r] = 0.f;

    const int KT = K >> 6;
    loadA(0, 0); loadB(0, 0); CP_COMMIT();
    loadA(1, 1); loadB(1, 1); CP_COMMIT();

    int st = 0, stn = 2;
    for (int i = 0; i < KT; i++) {
        if (i < KT - 1) { CP_WAIT(1); } else { CP_WAIT(0); }
        __syncthreads();
        if (i + 2 < KT) {
            loadA(stn, i + 2); loadB(stn, i + 2); CP_COMMIT();
            stn = (stn == 2) ? 0 : stn + 1;
        }
        uint32_t Abase = su + st * STB;
        uint32_t Bbase = Abase + 16384;
        st = (st == 2) ? 0 : st + 1;
#pragma unroll
        for (int kk = 0; kk < 4; kk++) {
            uint32_t af[4][4], bf[4][2];
            int cA = ((kk * 2 + ti.cxA) ^ ti.lr) << 4;
            int cB = ((kk * 2 + ti.cxB) ^ ti.lr) << 4;
#pragma unroll
            for (int mt = 0; mt < 4; mt++)
                LDM4(af[mt][0], af[mt][1], af[mt][2], af[mt][3], Abase + ti.rA[mt] + cA);
            LDM4(bf[0][0], bf[0][1], bf[1][0], bf[1][1], Bbase + ti.rB[0] + cB);
            LDM4(bf[2][0], bf[2][1], bf[3][0], bf[3][1], Bbase + ti.rB[1] + cB);
#pragma unroll
            for (int mt = 0; mt < 4; mt++)
#pragma unroll
                for (int nt = 0; nt < 4; nt++)
                    MMA16(acc[mt][nt], af[mt], bf[nt]);
        }
    }

    float* Cf = (float*)C;
    __half* Ch = (__half*)C;
#pragma unroll
    for (int mt = 0; mt < 4; mt++) {
        int row0 = m0 + ti.wm + mt * 16 + ti.l4q;
        int row1 = row0 + 8;
#pragma unroll
        for (int nt = 0; nt < 4; nt++) {
            int col = n0 + ti.wn + nt * 8 + ti.lmq * 2;
            float b0 = bias[col], b1 = bias[col + 1];
            float v0 = acc[mt][nt][0] + b0, v1 = acc[mt][nt][1] + b1;
            float v2 = acc[mt][nt][2] + b0, v3 = acc[mt][nt][3] + b1;
            if (EPI == 1) {
                *reinterpret_cast<float2*>(Cf + (long long)row0 * ldc + col) = make_float2(v0, v1);
                *reinterpret_cast<float2*>(Cf + (long long)row1 * ldc + col) = make_float2(v2, v3);
            } else {
                *reinterpret_cast<__half2*>(Ch + (long long)row0 * ldc + col) = __floats2half2_rn(v0, v1);
                *reinterpret_cast<__half2*>(Ch + (long long)row1 * ldc + col) = __floats2half2_rn(v2, v3);
            }
        }
    }
}

// ---------------- shared GEMM body for fused P+attn ---------------------------
// EPI: 2 half out, 3 mask+half out+rowsum->den.
template <int EPI>
__device__ __forceinline__ void gemm_body(
    int m0, int n0, int u,
    const __half* __restrict__ Ab, int lda,
    const __half* __restrict__ Bb, int ldb,
    __half* __restrict__ C, int ldc, long long sC,
    float* __restrict__ den, int K,
    uint32_t su, int tid) {
    const TileIdx ti(tid);

    auto loadA = [&](int st, int kt) {
        uint32_t dst = su + st * STB;
        int k0 = kt * 64;
#pragma unroll
        for (int p = 0; p < 4; p++) {
            int c = tid + p * 256;
            int row = c >> 3, ch = c & 7;
            CP16(dst + row * 128 + ((ch ^ (row & 7)) << 4),
                 Ab + (long long)(m0 + row) * lda + k0 + ch * 8);
        }
    };
    auto loadB = [&](int st, int kt) {
        uint32_t dst = su + st * STB + 16384;
        int k0 = kt * 64;
#pragma unroll
        for (int p = 0; p < 4; p++) {
            int c = tid + p * 256;
            int row = c >> 3, ch = c & 7;
            CP16(dst + row * 128 + ((ch ^ (row & 7)) << 4),
                 Bb + (long long)(n0 + row) * ldb + k0 + ch * 8);
        }
    };

    float acc[4][4][4];
#pragma unroll
    for (int mt = 0; mt < 4; mt++)
#pragma unroll
        for (int nt = 0; nt < 4; nt++)
#pragma unroll
            for (int r = 0; r < 4; r++) acc[mt][nt][r] = 0.f;

    const int KT = K >> 6;
    loadA(0, 0); loadB(0, 0); CP_COMMIT();
    loadA(1, 1); loadB(1, 1); CP_COMMIT();

    int st = 0, stn = 2;
    for (int i = 0; i < KT; i++) {
        if (i < KT - 1) { CP_WAIT(1); } else { CP_WAIT(0); }
        __syncthreads();
        if (i + 2 < KT) {
            loadA(stn, i + 2); loadB(stn, i + 2); CP_COMMIT();
            stn = (stn == 2) ? 0 : stn + 1;
        }
        uint32_t Abase = su + st * STB;
        uint32_t Bbase = Abase + 16384;
        st = (st == 2) ? 0 : st + 1;
#pragma unroll
        for (int kk = 0; kk < 4; kk++) {
            uint32_t af[4][4], bf[4][2];
            int cA = ((kk * 2 + ti.cxA) ^ ti.lr) << 4;
            int cB = ((kk * 2 + ti.cxB) ^ ti.lr) << 4;
#pragma unroll
            for (int mt = 0; mt < 4; mt++)
                LDM4(af[mt][0], af[mt][1], af[mt][2], af[mt][3], Abase + ti.rA[mt] + cA);
            LDM4(bf[0][0], bf[0][1], bf[1][0], bf[1][1], Bbase + ti.rB[0] + cB);
            LDM4(bf[2][0], bf[2][1], bf[3][0], bf[3][1], Bbase + ti.rB[1] + cB);
#pragma unroll
            for (int mt = 0; mt < 4; mt++)
#pragma unroll
                for (int nt = 0; nt < 4; nt++)
                    MMA16(acc[mt][nt], af[mt], bf[nt]);
        }
    }

    __half* Ch = C + (long long)u * sC;
#pragma unroll
    for (int mt = 0; mt < 4; mt++) {
        int row0 = m0 + ti.wm + mt * 16 + ti.l4q;
        int row1 = row0 + 8;
        float rs0 = 0.f, rs1 = 0.f;
#pragma unroll
        for (int nt = 0; nt < 4; nt++) {
            int col = n0 + ti.wn + nt * 8 + ti.lmq * 2;
            float v0 = acc[mt][nt][0], v1 = acc[mt][nt][1];
            float v2 = acc[mt][nt][2], v3 = acc[mt][nt][3];
            if (EPI == 3) {
                v0 = (col     > row0) ? 0.f : v0;
                v1 = (col + 1 > row0) ? 0.f : v1;
                v2 = (col     > row1) ? 0.f : v2;
                v3 = (col + 1 > row1) ? 0.f : v3;
            }
            __half2 h0 = __floats2half2_rn(v0, v1);
            __half2 h1 = __floats2half2_rn(v2, v3);
            if (EPI == 3) {
                rs0 += __half2float(h0.x) + __half2float(h0.y);
                rs1 += __half2float(h1.x) + __half2float(h1.y);
            }
            *reinterpret_cast<__half2*>(Ch + (long long)row0 * ldc + col) = h0;
            *reinterpret_cast<__half2*>(Ch + (long long)row1 * ldc + col) = h1;
        }
        if (EPI == 3) {
            rs0 += __shfl_xor_sync(0xffffffffu, rs0, 1);
            rs0 += __shfl_xor_sync(0xffffffffu, rs0, 2);
            rs1 += __shfl_xor_sync(0xffffffffu, rs1, 1);
            rs1 += __shfl_xor_sync(0xffffffffu, rs1, 2);
            if (ti.lmq == 0) {
                atomicAdd(den + (long long)u * CHUNK + row0, rs0);
                atomicAdd(den + (long long)u * CHUNK + row1, rs1);
            }
        }
    }
}

// ---------------- fused P+attn launch: attn blocks FIRST, dense P mapping -----
// bid in [0,320): attn (u = bid/10, tril block bid%10, K=1024, 16 ktiles)
// bid in [320,2112): P (dense 28 chunks x 64 blocks, K=512, 8 ktiles)
__global__ void __launch_bounds__(256, 2) pa_gemm(
    const __half* __restrict__ qkvh,
    const __half* __restrict__ kT, const __half* __restrict__ vT,
    __half* __restrict__ Ph, __half* __restrict__ attnh,
    float* __restrict__ den) {
    extern __shared__ char sm[];
    const uint32_t su = smem_u32(sm);
    const int tid = threadIdx.x;
    const int bid = blockIdx.x;

    if (bid < 320) {
        int u = bid / 10;
        int j = bid - u * 10;
        const __half* qb = qkvh + (long long)u * CHUNK * 4096;
        gemm_body<3>(c_bm[j] * 128, c_bn[j] * 128, u,
                     qb, 4096, qb + 1024, 4096,
                     attnh, CHUNK, (long long)CHUNK * CHUNK,
                     den, 1024, su, tid);
    } else {
        int e = bid - 320;
        int u7 = e >> 6;              // 0..27 dense chunk index
        int blk = e & 63;
        int ub = u7 / 7, uc = u7 - ub * 7;
        int u = ub * 8 + uc;
        gemm_body<2>((blk >> 3) * 128, (blk & 7) * 128, u,
                     vT + (long long)ub * 4194304 + uc * CHUNK, 4096,
                     kT + (long long)ub * 4194304 + uc * CHUNK, 4096,
                     Ph, 1024, 1048576LL, nullptr, CHUNK, su, tid);
    }
}

// ---------------- fused num kernel: num = (Q@S + attn@V) / den -> fp16 --------
__global__ void __launch_bounds__(256, 2) num_kernel(
    const __half* __restrict__ qkvh, const __half* __restrict__ Ph,
    const __half* __restrict__ attnh, const __half* __restrict__ vT,
    const float* __restrict__ den, __half* __restrict__ numh) {
    extern __shared__ char sm[];
    const uint32_t su = smem_u32(sm);
    const int tid = threadIdx.x;
    const int u = blockIdx.z;
    const int ub = u >> 3, uc = u & 7;
    const int m0 = blockIdx.y * 128;
    const int n0 = blockIdx.x * 128;
    const TileIdx ti(tid);

    float acc[4][4][4];
#pragma unroll
    for (int mt = 0; mt < 4; mt++)
#pragma unroll
        for (int nt = 0; nt < 4; nt++)
#pragma unroll
            for (int r = 0; r < 4; r++) acc[mt][nt][r] = 0.f;

    auto phase = [&](const __half* Ab, int lda, const __half* Bb, int ldb, int KT) {
        __syncthreads();   // stage-reuse guard at phase boundary
        auto loadA = [&](int st, int kt) {
            uint32_t dst = su + st * STB;
            int k0 = kt * 64;
#pragma unroll
            for (int p = 0; p < 4; p++) {
                int c = tid + p * 256;
                int row = c >> 3, ch = c & 7;
                CP16(dst + row * 128 + ((ch ^ (row & 7)) << 4),
                     Ab + (long long)(m0 + row) * lda + k0 + ch * 8);
            }
        };
        auto loadB = [&](int st, int kt) {
            uint32_t dst = su + st * STB + 16384;
            int k0 = kt * 64;
#pragma unroll
            for (int p = 0; p < 4; p++) {
                int c = tid + p * 256;
                int row = c >> 3, ch = c & 7;
                CP16(dst + row * 128 + ((ch ^ (row & 7)) << 4),
                     Bb + (long long)(n0 + row) * ldb + k0 + ch * 8);
            }
        };
        loadA(0, 0); loadB(0, 0); CP_COMMIT();
        if (KT > 1) { loadA(1, 1); loadB(1, 1); CP_COMMIT(); }
        int st = 0, stn = 2;
        for (int i = 0; i < KT; i++) {
            if (i < KT - 1) { CP_WAIT(1); } else { CP_WAIT(0); }
            __syncthreads();
            if (i + 2 < KT) {
                loadA(stn, i + 2); loadB(stn, i + 2); CP_COMMIT();
                stn = (stn == 2) ? 0 : stn + 1;
            }
            uint32_t Abase = su + st * STB;
            uint32_t Bbase = Abase + 16384;
            st = (st == 2) ? 0 : st + 1;
#pragma unroll
            for (int kk = 0; kk < 4; kk++) {
                uint32_t af[4][4], bf[4][2];
                int cA = ((kk * 2 + ti.cxA) ^ ti.lr) << 4;
                int cB = ((kk * 2 + ti.cxB) ^ ti.lr) << 4;
#pragma unroll
                for (int mt = 0; mt < 4; mt++)
                    LDM4(af[mt][0], af[mt][1], af[mt][2], af[mt][3], Abase + ti.rA[mt] + cA);
                LDM4(bf[0][0], bf[0][1], bf[1][0], bf[1][1], Bbase + ti.rB[0] + cB);
                LDM4(bf[2][0], bf[2][1], bf[3][0], bf[3][1], Bbase + ti.rB[1] + cB);
#pragma unroll
                for (int mt = 0; mt < 4; mt++)
#pragma unroll
                    for (int nt = 0; nt < 4; nt++)
                        MMA16(acc[mt][nt], af[mt], bf[nt]);
            }
        }
    };

    // Phase 1: Q @ S   (S_0 = 0 -> skip for first chunk of each batch)
    if (uc != 0)
        phase(qkvh + (long long)u * CHUNK * 4096, 4096,
              Ph + (long long)u * 1048576, 1024, 16);
    // Phase 2: attn @ V  (causal-truncated K)
    int K2 = m0 + 128;
    phase(attnh + (long long)u * CHUNK * CHUNK, CHUNK,
          vT + (long long)ub * 4194304 + uc * CHUNK, 4096, K2 >> 6);

    // epilogue: / den -> fp16
    __half* Ch = numh + (long long)u * CHUNK * 1024;
#pragma unroll
    for (int mt = 0; mt < 4; mt++) {
        int row0 = m0 + ti.wm + mt * 16 + ti.l4q;
        int row1 = row0 + 8;
        float rcp0 = __frcp_rn(den[(long long)u * CHUNK + row0]);
        float rcp1 = __frcp_rn(den[(long long)u * CHUNK + row1]);
#pragma unroll
        for (int nt = 0; nt < 4; nt++) {
            int col = n0 + ti.wn + nt * 8 + ti.lmq * 2;
            __half2 h0 = __floats2half2_rn(acc[mt][nt][0] * rcp0, acc[mt][nt][1] * rcp0);
            __half2 h1 = __floats2half2_rn(acc[mt][nt][2] * rcp1, acc[mt][nt][3] * rcp1);
            *reinterpret_cast<__half2*>(Ch + (long long)row0 * 1024 + col) = h0;
            *reinterpret_cast<__half2*>(Ch + (long long)row1 * 1024 + col) = h1;
        }
    }
}

// ---------------- LayerNorm -> fp16 (warp-per-row, shuffle-only) ---------------
__global__ void ln_kernel(const float* __restrict__ x,
                          const float* __restrict__ g,
                          const float* __restrict__ b,
                          __half* __restrict__ xn) {
    int warp = threadIdx.x >> 5, lane = threadIdx.x & 31;
    long long row = (long long)blockIdx.x * 8 + warp;
    const float4* xr = reinterpret_cast<const float4*>(x + row * D_MODEL);
    float4 v[8];
    float s = 0.f, ss = 0.f;
#pragma unroll
    for (int i = 0; i < 8; i++) {
        float4 t = xr[lane + i * 32];
        v[i] = t;
        s  += t.x + t.y + t.z + t.w;
        ss += t.x * t.x + t.y * t.y + t.z * t.z + t.w * t.w;
    }
#pragma unroll
    for (int o = 16; o > 0; o >>= 1) {
        s  += __shfl_xor_sync(0xffffffffu, s, o);
        ss += __shfl_xor_sync(0xffffffffu, ss, o);
    }
    float mu = s * (1.0f / D_MODEL);
    float var = ss * (1.0f / D_MODEL) - mu * mu;
    float inv = rsqrtf(var + LN_EPS);
    const float4* gg = reinterpret_cast<const float4*>(g);
    const float4* bb = reinterpret_cast<const float4*>(b);
    uint2* outr = reinterpret_cast<uint2*>(xn + row * D_MODEL);
#pragma unroll
    for (int i = 0; i < 8; i++) {
        int e = lane + i * 32;
        float4 gv = gg[e], bv = bb[e];
        __half2 h0 = __floats2half2_rn((v[i].x - mu) * inv * gv.x + bv.x,
                                       (v[i].y - mu) * inv * gv.y + bv.y);
        __half2 h1 = __floats2half2_rn((v[i].z - mu) * inv * gv.z + bv.z,
                                       (v[i].w - mu) * inv * gv.w + bv.w);
        uint2 o;
        o.x = *reinterpret_cast<uint32_t*>(&h0);
        o.y = *reinterpret_cast<uint32_t*>(&h1);
        outr[e] = o;
    }
}

// ---------------- fused prepack: wt | wpT | bias | zero Pk --------------------
#define PK_N1 (4096LL * 1024)
#define PK_N2 (PK_N1 + 1024LL * 1024)
#define PK_N3 (PK_N2 + 4096)
#define PK_N4 (PK_N3 + (long long)NUNITS * D_MODEL)
__global__ void pack_all(const float* __restrict__ wq, const float* __restrict__ wg,
                         const float* __restrict__ wp,
                         const float* __restrict__ bq, const float* __restrict__ bg,
                         __half* __restrict__ wt, __half* __restrict__ wpT,
                         float* __restrict__ bc, float* __restrict__ pk) {
    long long idx = (long long)blockIdx.x * 256 + threadIdx.x;
    if (idx < PK_N1) {
        int n = (int)(idx >> 10);
        int k = (int)(idx & 1023);
        float v = (n < 3072) ? wq[(long long)k * 3072 + n] : wg[(long long)k * 1024 + n - 3072];
        wt[idx] = __float2half_rn(v);
    } else if (idx < PK_N2) {
        long long e = idx - PK_N1;
        int n = (int)(e >> 10);
        int k = (int)(e & 1023);
        wpT[e] = __float2half_rn(wp[(long long)k * 1024 + n]);
    } else if (idx < PK_N3) {
        int n = (int)(idx - PK_N2);
        bc[n] = (n < 3072) ? bq[n] : bg[n - 3072];
    } else if (idx < PK_N4) {
        pk[idx - PK_N3] = 0.f;
    }
}

// ---------------- fused activations + kv transpose + chunk K colsums ----------
__global__ void actT_kernel(__half* __restrict__ qkvh,
                            __half* __restrict__ kT, __half* __restrict__ vT,
                            float* __restrict__ pk) {
    __shared__ __half sk[64][65], sv[64][65];   // [d][t]
    __shared__ float ssum[8][64];
    int tx = threadIdx.x, ty = threadIdx.y;
    int t0 = blockIdx.x * 64, d0 = blockIdx.y * 64;
    float k0s = 0.f, k1s = 0.f;
#pragma unroll
    for (int i = 0; i < 8; i++) {
        int t = ty + i * 8;
        __half2* base = reinterpret_cast<__half2*>(qkvh + (long long)(t0 + t) * 4096);
        int dh = (d0 >> 1) + tx;
        __half2 qv = base[dh];
        __half2 kv = base[512 + dh];
        __half2 vv = base[1024 + dh];
        __half2 gv = base[1536 + dh];
        float q0 = __low2float(qv), q1 = __high2float(qv);
        float k0 = __low2float(kv), k1 = __high2float(kv);
        float g0 = __low2float(gv), g1 = __high2float(gv);
        float kg0 = k0 * __frcp_rn(1.f + __expf(-g0));
        float kg1 = k1 * __frcp_rn(1.f + __expf(-g1));
        q0  = (q0  > 0.f) ? (q0  + 1.f) : __expf(q0);
        q1  = (q1  > 0.f) ? (q1  + 1.f) : __expf(q1);
        kg0 = (kg0 > 0.f) ? (kg0 + 1.f) : __expf(kg0);
        kg1 = (kg1 > 0.f) ? (kg1 + 1.f) : __expf(kg1);
        __half2 qh = __floats2half2_rn(q0, q1);
        __half2 kh = __floats2half2_rn(kg0, kg1);
        base[dh] = qh;
        base[512 + dh] = kh;
        sk[2 * tx][t]     = __low2half(kh);
        sk[2 * tx + 1][t] = __high2half(kh);
        sv[2 * tx][t]     = __low2half(vv);
        sv[2 * tx + 1][t] = __high2half(vv);
        k0s += __half2float(__low2half(kh));
        k1s += __half2float(__high2half(kh));
    }
    ssum[ty][2 * tx]     = k0s;
    ssum[ty][2 * tx + 1] = k1s;
    __syncthreads();
    int tpair = t0 + 2 * tx;
    int b = tpair >> 12, t = tpair & 4095;
    int lt = 2 * tx;
#pragma unroll
    for (int i = 0; i < 8; i++) {
        int dd = ty + i * 8;
        int d = d0 + dd;
        long long o = ((long long)b * 1024 + d) * 4096 + t;
        *reinterpret_cast<__half2*>(kT + o) = __halves2half2(sk[dd][lt], sk[dd][lt + 1]);
        *reinterpret_cast<__half2*>(vT + o) = __halves2half2(sv[dd][lt], sv[dd][lt + 1]);
    }
    if (ty == 0) {
        float s0 = 0.f, s1 = 0.f;
#pragma unroll
        for (int j = 0; j < 8; j++) { s0 += ssum[j][tx]; s1 += ssum[j][tx + 32]; }
        int u = t0 >> 9;
        atomicAdd(&pk[u * D_MODEL + d0 + tx], s0);
        atomicAdd(&pk[u * D_MODEL + d0 + 32 + tx], s1);
    }
}

// ---------------- exclusive prefix over chunk planes (half2, in place) --------
#define PLANE2 524288   /* half2 elements per plane */
__global__ void prefix_p(__half2* __restrict__ P) {
    long long e = (long long)blockIdx.x * 256 + threadIdx.x;
    int b = (int)(e >> 19);
    long long off = e & (PLANE2 - 1);
    __half2* base = P + (long long)b * NCHUNK * PLANE2 + off;
    float r0 = 0.f, r1 = 0.f;
    __half2 nxt = base[0];
#pragma unroll
    for (int c = 1; c < NCHUNK; c++) {
        r0 += __low2float(nxt);
        r1 += __high2float(nxt);
        if (c < NCHUNK - 1) nxt = base[(long long)c * PLANE2];
        base[(long long)c * PLANE2] = __floats2half2_rn(r0, r1);
    }
}

__global__ void prefix_k(float* __restrict__ Pk) {
    int e = blockIdx.x * 256 + threadIdx.x;
    int b = e >> 10;
    int d = e & 1023;
    float* base = Pk + b * NCHUNK * D_MODEL + d;
    float run = 0.f;
#pragma unroll
    for (int c = 0; c < NCHUNK; c++) {
        float t = base[c * D_MODEL];
        base[c * D_MODEL] = run;
        run += t;
    }
}

// ---------------- den = eps + q . Sk (half2 reads) -----------------------------
__global__ void den_kernel(const __half* __restrict__ qkvh,
                           const float* __restrict__ pk,
                           float* __restrict__ den) {
    int warp = blockIdx.x * 8 + (threadIdx.x >> 5);
    int lane = threadIdx.x & 31;
    const __half2* q = reinterpret_cast<const __half2*>(qkvh + (long long)warp * 4096);
    const float* sk = pk + (warp / CHUNK) * D_MODEL;
    float s = 0.f;
#pragma unroll 4
    for (int i = lane; i < 512; i += 32) {
        __half2 v = q[i];
        s += __low2float(v) * sk[2 * i] + __high2float(v) * sk[2 * i + 1];
    }
#pragma unroll
    for (int o = 16; o > 0; o >>= 1) s += __shfl_xor_sync(0xffffffffu, s, o);
    if (lane == 0) den[warp] = s + DEN_EPS;
}

// ---------------- launch ------------------------------------------------------
extern "C" void kernel_launch(void* const* d_in, const int* in_sizes, int n_in,
                              void* d_out, int out_size) {
    const float* x      = (const float*)d_in[0];
    const float* w_qkv  = (const float*)d_in[1];
    const float* b_qkv  = (const float*)d_in[2];
    const float* w_gate = (const float*)d_in[3];
    const float* b_gate = (const float*)d_in[4];
    const float* w_proj = (const float*)d_in[5];
    const float* b_proj = (const float*)d_in[6];
    const float* ln_g   = (const float*)d_in[7];
    const float* ln_b   = (const float*)d_in[8];
    float* out = (float*)d_out;

    __half *p_xnh, *p_qkvh, *p_kT, *p_vT, *p_Ph, *p_attnh, *p_numh, *p_wth, *p_wph;
    float *p_Pk, *p_den, *p_bcat;
    cudaGetSymbolAddress((void**)&p_xnh,   g_xnh);
    cudaGetSymbolAddress((void**)&p_qkvh,  g_qkvh);
    cudaGetSymbolAddress((void**)&p_kT,    g_kT);
    cudaGetSymbolAddress((void**)&p_vT,    g_vT);
    cudaGetSymbolAddress((void**)&p_Ph,    g_Ph);
    cudaGetSymbolAddress((void**)&p_Pk,    g_Pk);
    cudaGetSymbolAddress((void**)&p_attnh, g_attnh);
    cudaGetSymbolAddress((void**)&p_numh,  g_numh);
    cudaGetSymbolAddress((void**)&p_den,   g_den);
    cudaGetSymbolAddress((void**)&p_wth,   g_wth);
    cudaGetSymbolAddress((void**)&p_wph,   g_wph);
    cudaGetSymbolAddress((void**)&p_bcat,  g_bcat);

    cudaFuncSetAttribute(hgemm<1>, cudaFuncAttributeMaxDynamicSharedMemorySize, SMEM_BYTES);
    cudaFuncSetAttribute(hgemm<5>, cudaFuncAttributeMaxDynamicSharedMemorySize, SMEM_BYTES);
    cudaFuncSetAttribute(pa_gemm, cudaFuncAttributeMaxDynamicSharedMemorySize, SMEM_BYTES);
    cudaFuncSetAttribute(num_kernel, cudaFuncAttributeMaxDynamicSharedMemorySize, SMEM_BYTES);

    // 0. LayerNorm (warp-per-row)
    ln_kernel<<<NROWS / 8, 256>>>(x, ln_g, ln_b, p_xnh);
    // 1. all prepack + Pk zero
    pack_all<<<(int)((PK_N4 + 255) / 256), 256>>>(w_qkv, w_gate, w_proj,
                                                  b_qkv, b_gate,
                                                  p_wth, p_wph, p_bcat, p_Pk);

    // 2. qkvg = xn @ [w_qkv|w_gate] + bias -> qkvh fp16
    hgemm<5><<<dim3(32, 128, 1), 256, SMEM_BYTES>>>(
        p_xnh, 1024, p_wth, 1024, p_qkvh, 4096, p_bcat, 1024);

    // 3. fused activations + kv transpose + chunk colsums
    actT_kernel<<<dim3(NROWS / 64, D_MODEL / 64), dim3(32, 8)>>>(p_qkvh, p_kT, p_vT, p_Pk);

    // 4-5. prefix_k -> den (must precede attn atomics in pa_gemm)
    prefix_k<<<(B_SZ * D_MODEL) / 256, 256>>>(p_Pk);
    den_kernel<<<NROWS / 8, 256>>>(p_qkvh, p_Pk, p_den);

    // 6. fused attn (first) + P-GEMM (dense mapping) in one launch
    pa_gemm<<<2112, 256, SMEM_BYTES>>>(p_qkvh, p_kT, p_vT, p_Ph, p_attnh, p_den);

    // 7. exclusive prefix of P planes
    prefix_p<<<(B_SZ * PLANE2) / 256, 256>>>(reinterpret_cast<__half2*>(p_Ph));

    // 8. num = (Q@S + attn@V) / den -> fp16
    num_kernel<<<dim3(8, 4, NUNITS), 256, SMEM_BYTES>>>(
        p_qkvh, p_Ph, p_attnh, p_vT, p_den, p_numh);

    // 9. out = numh @ w_proj + b_proj
    hgemm<1><<<dim3(8, 128, 1), 256, SMEM_BYTES>>>(
        p_numh, 1024, p_wph, 1024, out, 1024, b_proj, 1024);
}